// round 3
// baseline (speedup 1.0000x reference)
#include <cuda_runtime.h>
#include <math.h>

#define NMAX 50000
#define EPS_LN 1e-5f

typedef unsigned long long u64;

// Scratch: P = x @ sp_w1[0:64,:] + sp_b1, Q = x @ sp_w1[64:128,:]   (each [N,256])
__device__ float g_P[(size_t)NMAX * 256];
__device__ float g_Q[(size_t)NMAX * 256];

// ---------------- f32x2 packed helpers (Blackwell sm_103a) ----------------
__device__ __forceinline__ u64 f2pack(float lo, float hi) {
    u64 r; asm("mov.b64 %0, {%1, %2};" : "=l"(r) : "f"(lo), "f"(hi)); return r;
}
__device__ __forceinline__ void f2unpack(u64 v, float& lo, float& hi) {
    asm("mov.b64 {%0, %1}, %2;" : "=f"(lo), "=f"(hi) : "l"(v));
}
__device__ __forceinline__ u64 dup2(float v) { return f2pack(v, v); }
__device__ __forceinline__ u64 fma2(u64 a, u64 b, u64 c) {
    u64 d; asm("fma.rn.f32x2 %0, %1, %2, %3;" : "=l"(d) : "l"(a), "l"(b), "l"(c)); return d;
}
__device__ __forceinline__ u64 add2(u64 a, u64 b) {
    u64 d; asm("add.rn.f32x2 %0, %1, %2;" : "=l"(d) : "l"(a), "l"(b)); return d;
}
__device__ __forceinline__ u64 mul2(u64 a, u64 b) {
    u64 d; asm("mul.rn.f32x2 %0, %1, %2;" : "=l"(d) : "l"(a), "l"(b)); return d;
}
__device__ __forceinline__ float rcp_fast(float x) {
    float r; asm("rcp.approx.f32 %0, %1;" : "=f"(r) : "f"(x)); return r;
}
__device__ __forceinline__ float ex2_fast(float x) {
    float r; asm("ex2.approx.f32 %0, %1;" : "=f"(r) : "f"(x)); return r;
}

__device__ __forceinline__ float wredsum(float v) {
#pragma unroll
    for (int o = 16; o > 0; o >>= 1) v += __shfl_xor_sync(0xffffffffu, v, o);
    return v;
}

// scalar fast exact-GELU (A&S 7.1.26 erf), for node kernels
__device__ __forceinline__ float gelu_fast(float u) {
    float z = 0.70710678118654752f * u;
    float az = fabsf(z);
    float t = rcp_fast(fmaf(0.3275911f, az, 1.0f));
    float poly = t * fmaf(t, fmaf(t, fmaf(t, fmaf(t, 1.061405429f, -1.453152027f),
                                          1.421413741f),
                                  -0.284496736f),
                          0.254829592f);
    float e = ex2_fast(-az * az * 1.4426950408889634f);
    float erf_z = copysignf(fmaf(-poly, e, 1.0f), z);
    return 0.5f * u * (1.0f + erf_z);
}

// ============================================================================
// K1: P,Q = x @ W_top (+b1), x @ W_bot. Transposed pair-packed x tile; FFMA2.
// 128 threads, 16 nodes/block; thread owns cols t and t+128 of both P and Q.
// ============================================================================
__global__ __launch_bounds__(128) void k_pq(const float* __restrict__ x,
                                            const float* __restrict__ w,   // [128,256]
                                            const float* __restrict__ b1,  // [256]
                                            int N) {
    __shared__ float xs[64][16];  // xs[k][node]
    const int t = threadIdx.x;
    const int n0 = blockIdx.x * 16;

    {
        const float4* x4 = reinterpret_cast<const float4*>(x);
#pragma unroll
        for (int i = t; i < 256; i += 128) {
            int node = i >> 4, kq = i & 15;
            float4 v = make_float4(0.f, 0.f, 0.f, 0.f);
            if (n0 + node < N) v = x4[(size_t)(n0 + node) * 16 + kq];
            xs[kq * 4 + 0][node] = v.x;
            xs[kq * 4 + 1][node] = v.y;
            xs[kq * 4 + 2][node] = v.z;
            xs[kq * 4 + 3][node] = v.w;
        }
    }
    __syncthreads();

    u64 aP0[8], aP1[8], aQ0[8], aQ1[8];
#pragma unroll
    for (int p = 0; p < 8; p++) { aP0[p] = 0; aP1[p] = 0; aQ0[p] = 0; aQ1[p] = 0; }

    const int c0 = t, c1 = t + 128;
#pragma unroll 4
    for (int k = 0; k < 64; k++) {
        u64 wp0 = dup2(__ldg(&w[k * 256 + c0]));
        u64 wp1 = dup2(__ldg(&w[k * 256 + c1]));
        u64 wq0 = dup2(__ldg(&w[(64 + k) * 256 + c0]));
        u64 wq1 = dup2(__ldg(&w[(64 + k) * 256 + c1]));
#pragma unroll
        for (int p = 0; p < 8; p++) {
            u64 xv = *reinterpret_cast<const u64*>(&xs[k][2 * p]);
            aP0[p] = fma2(xv, wp0, aP0[p]);
            aP1[p] = fma2(xv, wp1, aP1[p]);
            aQ0[p] = fma2(xv, wq0, aQ0[p]);
            aQ1[p] = fma2(xv, wq1, aQ1[p]);
        }
    }

    const float bb0 = b1[c0], bb1 = b1[c1];
#pragma unroll
    for (int p = 0; p < 8; p++) {
        int na = n0 + 2 * p, nb = na + 1;
        float lo, hi;
        f2unpack(aP0[p], lo, hi);
        if (na < N) g_P[(size_t)na * 256 + c0] = lo + bb0;
        if (nb < N) g_P[(size_t)nb * 256 + c0] = hi + bb0;
        f2unpack(aP1[p], lo, hi);
        if (na < N) g_P[(size_t)na * 256 + c1] = lo + bb1;
        if (nb < N) g_P[(size_t)nb * 256 + c1] = hi + bb1;
        f2unpack(aQ0[p], lo, hi);
        if (na < N) g_Q[(size_t)na * 256 + c0] = lo;
        if (nb < N) g_Q[(size_t)nb * 256 + c0] = hi;
        f2unpack(aQ1[p], lo, hi);
        if (na < N) g_Q[(size_t)na * 256 + c1] = lo;
        if (nb < N) g_Q[(size_t)nb * 256 + c1] = hi;
    }
}

// ============================================================================
// K2: per-edge  out = GELU(LN(P[row]+Q[col])) . w2 + b2   — fully f32x2
// ============================================================================
#define EPW 16
__global__ __launch_bounds__(256) void k_edge(const int* __restrict__ ei, int E,
                                              const float* __restrict__ gm,
                                              const float* __restrict__ bt,
                                              const float* __restrict__ w2,
                                              const float* __restrict__ b2p,
                                              float* __restrict__ out) {
    const int lane = threadIdx.x & 31;
    const long warp = (long)blockIdx.x * (blockDim.x >> 5) + (threadIdx.x >> 5);

    const float4* gmv = reinterpret_cast<const float4*>(gm);
    const float4* btv = reinterpret_cast<const float4*>(bt);
    const float4* w2v = reinterpret_cast<const float4*>(w2);
    float4 rga = gmv[lane], rgb = gmv[32 + lane];
    float4 rba = btv[lane], rbb = btv[32 + lane];
    float4 rwa = w2v[lane], rwb = w2v[32 + lane];

    u64 g2[4] = {f2pack(rga.x, rga.y), f2pack(rga.z, rga.w),
                 f2pack(rgb.x, rgb.y), f2pack(rgb.z, rgb.w)};
    u64 be2[4] = {f2pack(rba.x, rba.y), f2pack(rba.z, rba.w),
                  f2pack(rbb.x, rbb.y), f2pack(rbb.z, rbb.w)};
    u64 hw2[4] = {f2pack(0.5f * rwa.x, 0.5f * rwa.y), f2pack(0.5f * rwa.z, 0.5f * rwa.w),
                  f2pack(0.5f * rwb.x, 0.5f * rwb.y), f2pack(0.5f * rwb.z, 0.5f * rwb.w)};

    const u64 ONE2 = dup2(1.0f);
    const u64 SQ2 = dup2(0.70710678118654752f);
    const u64 A1F = dup2(0.3275911f);
    const u64 NC1 = dup2(-0.254829592f);
    const u64 NC2 = dup2(0.284496736f);
    const u64 NC3 = dup2(-1.421413741f);
    const u64 NC4 = dup2(1.453152027f);
    const u64 NC5 = dup2(-1.061405429f);
    const u64 NL2E = dup2(-1.4426950408889634f);
    const u64 AMASK = 0x7FFFFFFF7FFFFFFFull;
    const u64 SMASK = 0x8000000080000000ull;

    const float b2 = __ldg(b2p);

    const ulonglong2* P2 = reinterpret_cast<const ulonglong2*>(g_P);
    const ulonglong2* Q2 = reinterpret_cast<const ulonglong2*>(g_Q);

    long e0 = warp * EPW;
    for (int i = 0; i < EPW; i++) {
        long e = e0 + i;
        if (e >= E) return;
        int r = __ldg(&ei[e]);
        int c = __ldg(&ei[(long)E + e]);

        ulonglong2 pa = P2[(size_t)r * 64 + lane];
        ulonglong2 pb = P2[(size_t)r * 64 + 32 + lane];
        ulonglong2 qa = Q2[(size_t)c * 64 + lane];
        ulonglong2 qb = Q2[(size_t)c * 64 + 32 + lane];

        u64 s[4];
        s[0] = add2(pa.x, qa.x);
        s[1] = add2(pa.y, qa.y);
        s[2] = add2(pb.x, qb.x);
        s[3] = add2(pb.y, qb.y);

        u64 sum2 = add2(add2(s[0], s[1]), add2(s[2], s[3]));
        u64 sq2 = fma2(s[0], s[0], fma2(s[1], s[1], fma2(s[2], s[2], mul2(s[3], s[3]))));
        float slo, shi, qlo, qhi;
        f2unpack(sum2, slo, shi);
        f2unpack(sq2, qlo, qhi);
        float sum = wredsum(slo + shi);
        float sq = wredsum(qlo + qhi);
        float mean = sum * (1.f / 256.f);
        float var = sq * (1.f / 256.f) - mean * mean;
        float rstd = rsqrtf(var + EPS_LN);

        u64 A2 = dup2(rstd);
        u64 C2 = dup2(-mean * rstd);

        u64 acc2 = 0;
#pragma unroll
        for (int p = 0; p < 4; p++) {
            u64 u2 = fma2(s[p], A2, C2);       // normalized
            u2 = fma2(u2, g2[p], be2[p]);      // *gamma + beta
            u64 z2 = mul2(u2, SQ2);
            u64 az2 = z2 & AMASK;
            u64 d2 = fma2(az2, A1F, ONE2);
            float dlo, dhi;
            f2unpack(d2, dlo, dhi);
            u64 t2 = f2pack(rcp_fast(dlo), rcp_fast(dhi));
            u64 p2 = fma2(t2, NC5, NC4);
            p2 = fma2(t2, p2, NC3);
            p2 = fma2(t2, p2, NC2);
            p2 = fma2(t2, p2, NC1);
            p2 = mul2(p2, t2);                 // n(t), so erf = 1 + n*e
            u64 zz2 = mul2(az2, az2);
            u64 m2 = mul2(zz2, NL2E);
            float mlo, mhi;
            f2unpack(m2, mlo, mhi);
            u64 e2 = f2pack(ex2_fast(mlo), ex2_fast(mhi));
            u64 erf2 = fma2(p2, e2, ONE2);     // |erf(z)|
            erf2 = erf2 | (z2 & SMASK);        // signed (erf>=0 here)
            u64 op2 = add2(erf2, ONE2);        // 1 + erf
            u64 term2 = mul2(u2, op2);
            acc2 = fma2(term2, hw2[p], acc2);  // 0.5*w2 folded
        }
        float alo, ahi;
        f2unpack(acc2, alo, ahi);
        float acc = wredsum(alo + ahi);
        if (lane == 0) out[e] = acc + b2;
    }
}

// ============================================================================
// K3: fr branch  x[64] -> Linear(128) -> LN -> GELU -> Linear(64)   (FFMA2)
// ============================================================================
__global__ __launch_bounds__(64) void k_fr(const float* __restrict__ x,
                                           const float* __restrict__ w1,  // [64,128]
                                           const float* __restrict__ b1,
                                           const float* __restrict__ gm,
                                           const float* __restrict__ bt,
                                           const float* __restrict__ w2,  // [128,64]
                                           const float* __restrict__ b2,
                                           float* __restrict__ out, int N) {
    __shared__ float xs[64][16];   // xs[k][node]
    __shared__ float hs[16][128];
    const int t = threadIdx.x;
    const int n0 = blockIdx.x * 16;

    {
        const float4* x4 = reinterpret_cast<const float4*>(x);
#pragma unroll
        for (int i = t; i < 256; i += 64) {
            int node = i >> 4, kq = i & 15;
            float4 v = make_float4(0.f, 0.f, 0.f, 0.f);
            if (n0 + node < N) v = x4[(size_t)(n0 + node) * 16 + kq];
            xs[kq * 4 + 0][node] = v.x;
            xs[kq * 4 + 1][node] = v.y;
            xs[kq * 4 + 2][node] = v.z;
            xs[kq * 4 + 3][node] = v.w;
        }
    }
    __syncthreads();

    // GEMM1: cols c0=t, c1=t+64, node-pair packed
    {
        u64 a0[8], a1[8];
#pragma unroll
        for (int p = 0; p < 8; p++) { a0[p] = 0; a1[p] = 0; }
        const int c0 = t, c1 = t + 64;
#pragma unroll 4
        for (int k = 0; k < 64; k++) {
            u64 w0 = dup2(__ldg(&w1[k * 128 + c0]));
            u64 wB = dup2(__ldg(&w1[k * 128 + c1]));
#pragma unroll
            for (int p = 0; p < 8; p++) {
                u64 xv = *reinterpret_cast<const u64*>(&xs[k][2 * p]);
                a0[p] = fma2(xv, w0, a0[p]);
                a1[p] = fma2(xv, wB, a1[p]);
            }
        }
        float bb0 = b1[c0], bb1 = b1[c1];
#pragma unroll
        for (int p = 0; p < 8; p++) {
            float lo, hi;
            f2unpack(a0[p], lo, hi);
            hs[2 * p][c0] = lo + bb0;
            hs[2 * p + 1][c0] = hi + bb0;
            f2unpack(a1[p], lo, hi);
            hs[2 * p][c1] = lo + bb1;
            hs[2 * p + 1][c1] = hi + bb1;
        }
    }
    __syncthreads();

    // LN + GELU (2 warps x 8 nodes), 4 elems/lane
    {
        const int warp = t >> 5, lane = t & 31;
        float rg[4], rb[4];
#pragma unroll
        for (int q = 0; q < 4; q++) { rg[q] = gm[lane + 32 * q]; rb[q] = bt[lane + 32 * q]; }
        for (int mm = 0; mm < 8; mm++) {
            int m = warp * 8 + mm;
            float v[4];
            float sum = 0.f, sq = 0.f;
#pragma unroll
            for (int q = 0; q < 4; q++) {
                v[q] = hs[m][lane + 32 * q];
                sum += v[q];
                sq = fmaf(v[q], v[q], sq);
            }
            sum = wredsum(sum);
            sq = wredsum(sq);
            float mean = sum * (1.f / 128.f);
            float var = sq * (1.f / 128.f) - mean * mean;
            float rstd = rsqrtf(var + EPS_LN);
#pragma unroll
            for (int q = 0; q < 4; q++) {
                float u = fmaf((v[q] - mean) * rstd, rg[q], rb[q]);
                hs[m][lane + 32 * q] = gelu_fast(u);
            }
        }
    }
    __syncthreads();

    // GEMM2: thread = (mgroup of 8 nodes, output pair o0,o0+1), FFMA2
    {
        const int mg = t >> 5;
        const int o0 = (t & 31) * 2;
        u64 acc2[8];
#pragma unroll
        for (int mm = 0; mm < 8; mm++) acc2[mm] = 0;
#pragma unroll 2
        for (int j4 = 0; j4 < 32; j4++) {
            u64 wj[4];
#pragma unroll
            for (int j = 0; j < 4; j++)
                wj[j] = *reinterpret_cast<const u64*>(&w2[(j4 * 4 + j) * 64 + o0]);
#pragma unroll
            for (int mm = 0; mm < 8; mm++) {
                int m = mg * 8 + mm;
                float4 gv = *reinterpret_cast<const float4*>(&hs[m][j4 * 4]);
                acc2[mm] = fma2(dup2(gv.x), wj[0], acc2[mm]);
                acc2[mm] = fma2(dup2(gv.y), wj[1], acc2[mm]);
                acc2[mm] = fma2(dup2(gv.z), wj[2], acc2[mm]);
                acc2[mm] = fma2(dup2(gv.w), wj[3], acc2[mm]);
            }
        }
        u64 bo2 = *reinterpret_cast<const u64*>(&b2[o0]);
#pragma unroll
        for (int mm = 0; mm < 8; mm++) {
            int n = n0 + mg * 8 + mm;
            if (n < N)
                *reinterpret_cast<u64*>(&out[(size_t)n * 64 + o0]) = add2(acc2[mm], bo2);
        }
    }
}

// ============================================================================
// K4: ph branch  x[64] -> Linear(256) -> LN -> GELU -> Linear(128)  (FFMA2)
// ============================================================================
__global__ __launch_bounds__(64) void k_ph(const float* __restrict__ x,
                                           const float* __restrict__ w1,  // [64,256]
                                           const float* __restrict__ b1,
                                           const float* __restrict__ gm,
                                           const float* __restrict__ bt,
                                           const float* __restrict__ w2,  // [256,128]
                                           const float* __restrict__ b2,
                                           float* __restrict__ out, int N) {
    __shared__ float xs[64][16];
    __shared__ float hs[16][256];
    const int t = threadIdx.x;
    const int n0 = blockIdx.x * 16;

    {
        const float4* x4 = reinterpret_cast<const float4*>(x);
#pragma unroll
        for (int i = t; i < 256; i += 64) {
            int node = i >> 4, kq = i & 15;
            float4 v = make_float4(0.f, 0.f, 0.f, 0.f);
            if (n0 + node < N) v = x4[(size_t)(n0 + node) * 16 + kq];
            xs[kq * 4 + 0][node] = v.x;
            xs[kq * 4 + 1][node] = v.y;
            xs[kq * 4 + 2][node] = v.z;
            xs[kq * 4 + 3][node] = v.w;
        }
    }
    __syncthreads();

    // GEMM1: 4 cols/thread (t, t+64, t+128, t+192), node-pair packed
    {
        u64 a[4][8];
#pragma unroll
        for (int cc = 0; cc < 4; cc++)
#pragma unroll
            for (int p = 0; p < 8; p++) a[cc][p] = 0;

#pragma unroll 4
        for (int k = 0; k < 64; k++) {
            u64 wr[4];
#pragma unroll
            for (int cc = 0; cc < 4; cc++)
                wr[cc] = dup2(__ldg(&w1[k * 256 + t + 64 * cc]));
#pragma unroll
            for (int p = 0; p < 8; p++) {
                u64 xv = *reinterpret_cast<const u64*>(&xs[k][2 * p]);
#pragma unroll
                for (int cc = 0; cc < 4; cc++) a[cc][p] = fma2(xv, wr[cc], a[cc][p]);
            }
        }
#pragma unroll
        for (int cc = 0; cc < 4; cc++) {
            float bb = b1[t + 64 * cc];
#pragma unroll
            for (int p = 0; p < 8; p++) {
                float lo, hi;
                f2unpack(a[cc][p], lo, hi);
                hs[2 * p][t + 64 * cc] = lo + bb;
                hs[2 * p + 1][t + 64 * cc] = hi + bb;
            }
        }
    }
    __syncthreads();

    // LN + GELU: 8 elems/lane
    {
        const int warp = t >> 5, lane = t & 31;
        float rg[8], rb[8];
#pragma unroll
        for (int q = 0; q < 8; q++) { rg[q] = gm[lane + 32 * q]; rb[q] = bt[lane + 32 * q]; }
        for (int mm = 0; mm < 8; mm++) {
            int m = warp * 8 + mm;
            float v[8];
            float sum = 0.f, sq = 0.f;
#pragma unroll
            for (int q = 0; q < 8; q++) {
                v[q] = hs[m][lane + 32 * q];
                sum += v[q];
                sq = fmaf(v[q], v[q], sq);
            }
            sum = wredsum(sum);
            sq = wredsum(sq);
            float mean = sum * (1.f / 256.f);
            float var = sq * (1.f / 256.f) - mean * mean;
            float rstd = rsqrtf(var + EPS_LN);
#pragma unroll
            for (int q = 0; q < 8; q++) {
                float u = fmaf((v[q] - mean) * rstd, rg[q], rb[q]);
                hs[m][lane + 32 * q] = gelu_fast(u);
            }
        }
    }
    __syncthreads();

    // GEMM2: OUT=128, thread = (mgroup, outputs o0..o0+3 as 2 pairs), FFMA2
    {
        const int mg = t >> 5;
        const int o0 = (t & 31) * 4;
        u64 acc2[8][2];
#pragma unroll
        for (int mm = 0; mm < 8; mm++) { acc2[mm][0] = 0; acc2[mm][1] = 0; }

#pragma unroll 2
        for (int j4 = 0; j4 < 64; j4++) {
            u64 wa[4], wb[4];
#pragma unroll
            for (int j = 0; j < 4; j++) {
                wa[j] = *reinterpret_cast<const u64*>(&w2[(j4 * 4 + j) * 128 + o0]);
                wb[j] = *reinterpret_cast<const u64*>(&w2[(j4 * 4 + j) * 128 + o0 + 2]);
            }
#pragma unroll
            for (int mm = 0; mm < 8; mm++) {
                int m = mg * 8 + mm;
                float4 gv = *reinterpret_cast<const float4*>(&hs[m][j4 * 4]);
                u64 g0 = dup2(gv.x), g1 = dup2(gv.y), g2d = dup2(gv.z), g3 = dup2(gv.w);
                acc2[mm][0] = fma2(g0, wa[0], acc2[mm][0]);
                acc2[mm][1] = fma2(g0, wb[0], acc2[mm][1]);
                acc2[mm][0] = fma2(g1, wa[1], acc2[mm][0]);
                acc2[mm][1] = fma2(g1, wb[1], acc2[mm][1]);
                acc2[mm][0] = fma2(g2d, wa[2], acc2[mm][0]);
                acc2[mm][1] = fma2(g2d, wb[2], acc2[mm][1]);
                acc2[mm][0] = fma2(g3, wa[3], acc2[mm][0]);
                acc2[mm][1] = fma2(g3, wb[3], acc2[mm][1]);
            }
        }
        u64 bo0 = *reinterpret_cast<const u64*>(&b2[o0]);
        u64 bo1 = *reinterpret_cast<const u64*>(&b2[o0 + 2]);
#pragma unroll
        for (int mm = 0; mm < 8; mm++) {
            int n = n0 + mg * 8 + mm;
            if (n < N) {
                ulonglong2 r;
                r.x = add2(acc2[mm][0], bo0);
                r.y = add2(acc2[mm][1], bo1);
                *reinterpret_cast<ulonglong2*>(&out[(size_t)n * 128 + o0]) = r;
            }
        }
    }
}

// ============================================================================
// launch
// ============================================================================
extern "C" void kernel_launch(void* const* d_in, const int* in_sizes, int n_in,
                              void* d_out, int out_size) {
    const float* x = (const float*)d_in[0];
    const int* ei = (const int*)d_in[1];
    const float* sp_w1 = (const float*)d_in[2];
    const float* sp_b1 = (const float*)d_in[3];
    const float* sp_g = (const float*)d_in[4];
    const float* sp_be = (const float*)d_in[5];
    const float* sp_w2 = (const float*)d_in[6];
    const float* sp_b2 = (const float*)d_in[7];
    const float* fr_w1 = (const float*)d_in[8];
    const float* fr_b1 = (const float*)d_in[9];
    const float* fr_g = (const float*)d_in[10];
    const float* fr_be = (const float*)d_in[11];
    const float* fr_w2 = (const float*)d_in[12];
    const float* fr_b2 = (const float*)d_in[13];
    const float* ph_w1 = (const float*)d_in[14];
    const float* ph_b1 = (const float*)d_in[15];
    const float* ph_g = (const float*)d_in[16];
    const float* ph_be = (const float*)d_in[17];
    const float* ph_w2 = (const float*)d_in[18];
    const float* ph_b2 = (const float*)d_in[19];

    const int N = in_sizes[0] / 64;
    const int E = in_sizes[1] / 2;

    float* out_sp = (float*)d_out;             // [E]
    float* out_fr = out_sp + (size_t)E;        // [N,64]
    float* out_ph = out_fr + (size_t)N * 64;   // [N,128]

    int nblk = (N + 15) / 16;
    k_pq<<<nblk, 128>>>(x, sp_w1, sp_b1, N);
    k_fr<<<nblk, 64>>>(x, fr_w1, fr_b1, fr_g, fr_be, fr_w2, fr_b2, out_fr, N);
    k_ph<<<nblk, 64>>>(x, ph_w1, ph_b1, ph_g, ph_be, ph_w2, ph_b2, out_ph, N);

    long warps = ((long)E + EPW - 1) / EPW;
    int eblocks = (int)((warps + 7) / 8);
    k_edge<<<eblocks, 256>>>(ei, E, sp_g, sp_be, sp_w2, sp_b2, out_sp);
}

// round 4
// speedup vs baseline: 1.0912x; 1.0912x over previous
#include <cuda_runtime.h>
#include <math.h>

#define NMAX 50000
#define EPS_LN 1e-5f
#define EPW 16

typedef unsigned long long u64;

// Scratch: P = x @ sp_w1[0:64,:] + sp_b1, Q = x @ sp_w1[64:128,:]   (each [N,256])
__device__ float g_P[(size_t)NMAX * 256];
__device__ float g_Q[(size_t)NMAX * 256];

// ---------------- f32x2 packed helpers ----------------
__device__ __forceinline__ u64 f2pack(float lo, float hi) {
    u64 r; asm("mov.b64 %0, {%1, %2};" : "=l"(r) : "f"(lo), "f"(hi)); return r;
}
__device__ __forceinline__ void f2unpack(u64 v, float& lo, float& hi) {
    asm("mov.b64 {%0, %1}, %2;" : "=f"(lo), "=f"(hi) : "l"(v));
}
__device__ __forceinline__ u64 dup2(float v) { return f2pack(v, v); }
__device__ __forceinline__ u64 fma2(u64 a, u64 b, u64 c) {
    u64 d; asm("fma.rn.f32x2 %0, %1, %2, %3;" : "=l"(d) : "l"(a), "l"(b), "l"(c)); return d;
}
__device__ __forceinline__ u64 add2(u64 a, u64 b) {
    u64 d; asm("add.rn.f32x2 %0, %1, %2;" : "=l"(d) : "l"(a), "l"(b)); return d;
}
__device__ __forceinline__ u64 mul2(u64 a, u64 b) {
    u64 d; asm("mul.rn.f32x2 %0, %1, %2;" : "=l"(d) : "l"(a), "l"(b)); return d;
}
__device__ __forceinline__ float rcp_fast(float x) {
    float r; asm("rcp.approx.f32 %0, %1;" : "=f"(r) : "f"(x)); return r;
}
__device__ __forceinline__ float ex2_fast(float x) {
    float r; asm("ex2.approx.f32 %0, %1;" : "=f"(r) : "f"(x)); return r;
}

__device__ __forceinline__ float wredsum(float v) {
#pragma unroll
    for (int o = 16; o > 0; o >>= 1) v += __shfl_xor_sync(0xffffffffu, v, o);
    return v;
}

// scalar fast exact-GELU (A&S 7.1.26 erf), for node roles
__device__ __forceinline__ float gelu_fast(float u) {
    float z = 0.70710678118654752f * u;
    float az = fabsf(z);
    float t = rcp_fast(fmaf(0.3275911f, az, 1.0f));
    float poly = t * fmaf(t, fmaf(t, fmaf(t, fmaf(t, 1.061405429f, -1.453152027f),
                                          1.421413741f),
                                  -0.284496736f),
                          0.254829592f);
    float e = ex2_fast(-az * az * 1.4426950408889634f);
    float erf_z = copysignf(fmaf(-poly, e, 1.0f), z);
    return 0.5f * u * (1.0f + erf_z);
}

// ============================================================================
// K1: P,Q = x @ W_top (+b1), x @ W_bot.  (R2 scalar version — FMA roofline)
// ============================================================================
__global__ __launch_bounds__(128) void k_pq(const float* __restrict__ x,
                                            const float* __restrict__ w,   // [128,256]
                                            const float* __restrict__ b1,  // [256]
                                            int N) {
    __shared__ float xs[16][64];
    const int t = threadIdx.x;
    const int n0 = blockIdx.x * 16;

    {
        float4* xs4 = reinterpret_cast<float4*>(&xs[0][0]);
        const float4* x4 = reinterpret_cast<const float4*>(x);
#pragma unroll
        for (int i = t; i < 256; i += 128) {
            int node = n0 + (i >> 4);
            float4 v = make_float4(0.f, 0.f, 0.f, 0.f);
            if (node < N) v = x4[(size_t)node * 16 + (i & 15)];
            xs4[i] = v;
        }
    }
    __syncthreads();

    float aP0[16], aP1[16], aQ0[16], aQ1[16];
#pragma unroll
    for (int m = 0; m < 16; m++) { aP0[m] = 0.f; aP1[m] = 0.f; aQ0[m] = 0.f; aQ1[m] = 0.f; }

    const int c0 = t, c1 = t + 128;
#pragma unroll 2
    for (int k4 = 0; k4 < 16; k4++) {
        float wp0[4], wp1[4], wq0[4], wq1[4];
#pragma unroll
        for (int j = 0; j < 4; j++) {
            int k = k4 * 4 + j;
            wp0[j] = w[k * 256 + c0];
            wp1[j] = w[k * 256 + c1];
            wq0[j] = w[(64 + k) * 256 + c0];
            wq1[j] = w[(64 + k) * 256 + c1];
        }
#pragma unroll
        for (int m = 0; m < 16; m++) {
            float4 xv = *reinterpret_cast<const float4*>(&xs[m][k4 * 4]);
            float xa[4] = {xv.x, xv.y, xv.z, xv.w};
#pragma unroll
            for (int j = 0; j < 4; j++) {
                aP0[m] = fmaf(xa[j], wp0[j], aP0[m]);
                aP1[m] = fmaf(xa[j], wp1[j], aP1[m]);
                aQ0[m] = fmaf(xa[j], wq0[j], aQ0[m]);
                aQ1[m] = fmaf(xa[j], wq1[j], aQ1[m]);
            }
        }
    }

    const float bb0 = b1[c0], bb1 = b1[c1];
#pragma unroll
    for (int m = 0; m < 16; m++) {
        int n = n0 + m;
        if (n >= N) break;
        g_P[(size_t)n * 256 + c0] = aP0[m] + bb0;
        g_P[(size_t)n * 256 + c1] = aP1[m] + bb1;
        g_Q[(size_t)n * 256 + c0] = aQ0[m];
        g_Q[(size_t)n * 256 + c1] = aQ1[m];
    }
}

// ============================================================================
// Edge role: out = GELU(LN(P[row]+Q[col])) . w2 + b2  — f32x2, folded consts
// 4 warps/block, EPW edges per warp.
// ============================================================================
__device__ __forceinline__ void edge_role(int eb, const int* __restrict__ ei, int E,
                                          const float* __restrict__ gm,
                                          const float* __restrict__ bt,
                                          const float* __restrict__ w2,
                                          const float* __restrict__ b2p,
                                          float* __restrict__ out) {
    const int t = threadIdx.x;
    const int lane = t & 31;
    const int wid = t >> 5;

    const float4* gmv = reinterpret_cast<const float4*>(gm);
    const float4* btv = reinterpret_cast<const float4*>(bt);
    const float4* w2v = reinterpret_cast<const float4*>(w2);
    float4 rga = gmv[lane], rgb = gmv[32 + lane];
    float4 rba = btv[lane], rbb = btv[32 + lane];
    float4 rwa = w2v[lane], rwb = w2v[32 + lane];

    const float RS2 = 0.70710678118654752f;  // 1/sqrt2; also = 0.5*sqrt2
    u64 g2[4] = {f2pack(rga.x * RS2, rga.y * RS2), f2pack(rga.z * RS2, rga.w * RS2),
                 f2pack(rgb.x * RS2, rgb.y * RS2), f2pack(rgb.z * RS2, rgb.w * RS2)};
    u64 be2[4] = {f2pack(rba.x * RS2, rba.y * RS2), f2pack(rba.z * RS2, rba.w * RS2),
                  f2pack(rbb.x * RS2, rbb.y * RS2), f2pack(rbb.z * RS2, rbb.w * RS2)};
    u64 hw2[4] = {f2pack(rwa.x * RS2, rwa.y * RS2), f2pack(rwa.z * RS2, rwa.w * RS2),
                  f2pack(rwb.x * RS2, rwb.y * RS2), f2pack(rwb.z * RS2, rwb.w * RS2)};

    const u64 ONE2 = dup2(1.0f);
    const u64 A1F = dup2(0.3275911f);
    const u64 NC1 = dup2(-0.254829592f);
    const u64 NC2 = dup2(0.284496736f);
    const u64 NC3 = dup2(-1.421413741f);
    const u64 NC4 = dup2(1.453152027f);
    const u64 NC5 = dup2(-1.061405429f);
    const u64 NL2E = dup2(-1.4426950408889634f);
    const u64 AMASK = 0x7FFFFFFF7FFFFFFFull;
    const u64 SMASK = 0x8000000080000000ull;

    const float b2 = __ldg(b2p);

    const ulonglong2* P2 = reinterpret_cast<const ulonglong2*>(g_P);
    const ulonglong2* Q2 = reinterpret_cast<const ulonglong2*>(g_Q);

    long e0 = ((long)eb * 4 + wid) * EPW;
    for (int i = 0; i < EPW; i++) {
        long e = e0 + i;
        if (e >= E) return;
        int r = __ldg(&ei[e]);
        int c = __ldg(&ei[(long)E + e]);

        ulonglong2 pa = P2[(size_t)r * 64 + lane];
        ulonglong2 pb = P2[(size_t)r * 64 + 32 + lane];
        ulonglong2 qa = Q2[(size_t)c * 64 + lane];
        ulonglong2 qb = Q2[(size_t)c * 64 + 32 + lane];

        u64 s[4];
        s[0] = add2(pa.x, qa.x);
        s[1] = add2(pa.y, qa.y);
        s[2] = add2(pb.x, qb.x);
        s[3] = add2(pb.y, qb.y);

        u64 sum2 = add2(add2(s[0], s[1]), add2(s[2], s[3]));
        u64 sq2 = fma2(s[0], s[0], fma2(s[1], s[1], fma2(s[2], s[2], mul2(s[3], s[3]))));
        float slo, shi, qlo, qhi;
        f2unpack(sum2, slo, shi);
        f2unpack(sq2, qlo, qhi);
        float sum = wredsum(slo + shi);
        float sq = wredsum(qlo + qhi);
        float mean = sum * (1.f / 256.f);
        float var = sq * (1.f / 256.f) - mean * mean;
        float rstd = rsqrtf(var + EPS_LN);

        u64 A2 = dup2(rstd);
        u64 C2 = dup2(-mean * rstd);

        u64 acc2 = 0;
#pragma unroll
        for (int p = 0; p < 4; p++) {
            u64 un2 = fma2(s[p], A2, C2);      // normalized
            u64 z2 = fma2(un2, g2[p], be2[p]); // z = (norm*g + be)/sqrt2 (folded)
            u64 az2 = z2 & AMASK;
            u64 d2 = fma2(az2, A1F, ONE2);
            float dlo, dhi;
            f2unpack(d2, dlo, dhi);
            u64 t2 = f2pack(rcp_fast(dlo), rcp_fast(dhi));
            u64 p2 = fma2(t2, NC5, NC4);
            p2 = fma2(t2, p2, NC3);
            p2 = fma2(t2, p2, NC2);
            p2 = fma2(t2, p2, NC1);
            p2 = mul2(p2, t2);                 // n(t): erf = 1 + n*e
            u64 zz2 = mul2(az2, az2);
            u64 m2 = mul2(zz2, NL2E);
            float mlo, mhi;
            f2unpack(m2, mlo, mhi);
            u64 e2 = f2pack(ex2_fast(mlo), ex2_fast(mhi));
            u64 erf2 = fma2(p2, e2, ONE2);     // |erf(z)|
            erf2 = erf2 | (z2 & SMASK);        // sign of z
            u64 op2 = add2(erf2, ONE2);        // 1 + erf
            u64 term2 = mul2(z2, op2);         // z*(1+erf)
            acc2 = fma2(term2, hw2[p], acc2);  // * (w2*sqrt2/2)  => 0.5*u*(1+erf)*w2
        }
        float alo, ahi;
        f2unpack(acc2, alo, ahi);
        float acc = wredsum(alo + ahi);
        if (lane == 0) out[e] = acc + b2;
    }
}

// ============================================================================
// fr role: x[64] -> Linear(128) -> LN -> GELU -> Linear(64)
// Two 64-thread subgroups, 16 nodes each (32 nodes/block). Scalar FMA (R2).
// ============================================================================
__device__ __forceinline__ void fr_role(int nb, char* smem_raw,
                                        const float* __restrict__ x,
                                        const float* __restrict__ w1,
                                        const float* __restrict__ b1,
                                        const float* __restrict__ gm,
                                        const float* __restrict__ bt,
                                        const float* __restrict__ w2,
                                        const float* __restrict__ b2,
                                        float* __restrict__ out, int N) {
    const int t = threadIdx.x;
    const int g = t >> 6;
    const int t64 = t & 63;
    float (*xs)[64] = reinterpret_cast<float (*)[64]>(smem_raw + g * 4096);            // [16][64]
    float (*hs)[128] = reinterpret_cast<float (*)[128]>(smem_raw + 8192 + g * 8192);   // [16][128]
    const int n0 = nb * 32 + g * 16;

    {
        float4* xs4 = reinterpret_cast<float4*>(&xs[0][0]);
        const float4* x4 = reinterpret_cast<const float4*>(x);
#pragma unroll
        for (int i = t64; i < 256; i += 64) {
            int node = n0 + (i >> 4);
            float4 v = make_float4(0.f, 0.f, 0.f, 0.f);
            if (node < N) v = x4[(size_t)node * 16 + (i & 15)];
            xs4[i] = v;
        }
    }
    __syncthreads();

    // GEMM1: 2 cols/thread
    {
        float a0[16], a1[16];
#pragma unroll
        for (int m = 0; m < 16; m++) { a0[m] = 0.f; a1[m] = 0.f; }
        const int c0 = t64, c1 = t64 + 64;
#pragma unroll 2
        for (int k4 = 0; k4 < 16; k4++) {
            float wr0[4], wr1[4];
#pragma unroll
            for (int j = 0; j < 4; j++) {
                int k = k4 * 4 + j;
                wr0[j] = w1[k * 128 + c0];
                wr1[j] = w1[k * 128 + c1];
            }
#pragma unroll
            for (int m = 0; m < 16; m++) {
                float4 xv = *reinterpret_cast<const float4*>(&xs[m][k4 * 4]);
                float xa[4] = {xv.x, xv.y, xv.z, xv.w};
#pragma unroll
                for (int j = 0; j < 4; j++) {
                    a0[m] = fmaf(xa[j], wr0[j], a0[m]);
                    a1[m] = fmaf(xa[j], wr1[j], a1[m]);
                }
            }
        }
        float bb0 = b1[c0], bb1 = b1[c1];
#pragma unroll
        for (int m = 0; m < 16; m++) { hs[m][c0] = a0[m] + bb0; hs[m][c1] = a1[m] + bb1; }
    }
    __syncthreads();

    // LN + GELU (2 warps per subgroup x 8 nodes), 4 elems/lane
    {
        const int w2i = t64 >> 5, lane = t & 31;
        float rg[4], rb[4];
#pragma unroll
        for (int q = 0; q < 4; q++) { rg[q] = gm[lane + 32 * q]; rb[q] = bt[lane + 32 * q]; }
        for (int mm = 0; mm < 8; mm++) {
            int m = w2i * 8 + mm;
            float v[4];
            float sum = 0.f, sq = 0.f;
#pragma unroll
            for (int q = 0; q < 4; q++) {
                v[q] = hs[m][lane + 32 * q];
                sum += v[q];
                sq = fmaf(v[q], v[q], sq);
            }
            sum = wredsum(sum);
            sq = wredsum(sq);
            float mean = sum * (1.f / 128.f);
            float var = sq * (1.f / 128.f) - mean * mean;
            float rstd = rsqrtf(var + EPS_LN);
#pragma unroll
            for (int q = 0; q < 4; q++) {
                float u = fmaf((v[q] - mean) * rstd, rg[q], rb[q]);
                hs[m][lane + 32 * q] = gelu_fast(u);
            }
        }
    }
    __syncthreads();

    // GEMM2: thread = (mgroup of 8 nodes, 2 outputs)
    {
        const int mg = t64 >> 5;
        const int o0 = (t & 31) * 2;
        float acc[8][2];
#pragma unroll
        for (int mm = 0; mm < 8; mm++) { acc[mm][0] = 0.f; acc[mm][1] = 0.f; }
#pragma unroll 2
        for (int j4 = 0; j4 < 32; j4++) {
            float2 wv[4];
#pragma unroll
            for (int j = 0; j < 4; j++)
                wv[j] = *reinterpret_cast<const float2*>(&w2[(j4 * 4 + j) * 64 + o0]);
#pragma unroll
            for (int mm = 0; mm < 8; mm++) {
                int m = mg * 8 + mm;
                float4 gv = *reinterpret_cast<const float4*>(&hs[m][j4 * 4]);
                acc[mm][0] = fmaf(gv.x, wv[0].x, acc[mm][0]);
                acc[mm][0] = fmaf(gv.y, wv[1].x, acc[mm][0]);
                acc[mm][0] = fmaf(gv.z, wv[2].x, acc[mm][0]);
                acc[mm][0] = fmaf(gv.w, wv[3].x, acc[mm][0]);
                acc[mm][1] = fmaf(gv.x, wv[0].y, acc[mm][1]);
                acc[mm][1] = fmaf(gv.y, wv[1].y, acc[mm][1]);
                acc[mm][1] = fmaf(gv.z, wv[2].y, acc[mm][1]);
                acc[mm][1] = fmaf(gv.w, wv[3].y, acc[mm][1]);
            }
        }
        float bo0 = b2[o0], bo1 = b2[o0 + 1];
#pragma unroll
        for (int mm = 0; mm < 8; mm++) {
            int n = n0 + mg * 8 + mm;
            if (n < N) {
                out[(size_t)n * 64 + o0] = acc[mm][0] + bo0;
                out[(size_t)n * 64 + o0 + 1] = acc[mm][1] + bo1;
            }
        }
    }
}

// ============================================================================
// ph role: x[64] -> Linear(256) -> LN -> GELU -> Linear(128)
// Two 64-thread subgroups, 8 nodes each (16 nodes/block). Scalar FMA.
// ============================================================================
__device__ __forceinline__ void ph_role(int nb, char* smem_raw,
                                        const float* __restrict__ x,
                                        const float* __restrict__ w1,
                                        const float* __restrict__ b1,
                                        const float* __restrict__ gm,
                                        const float* __restrict__ bt,
                                        const float* __restrict__ w2,
                                        const float* __restrict__ b2,
                                        float* __restrict__ out, int N) {
    const int t = threadIdx.x;
    const int g = t >> 6;
    const int t64 = t & 63;
    float (*xs)[64] = reinterpret_cast<float (*)[64]>(smem_raw + g * 2048);            // [8][64]
    float (*hs)[256] = reinterpret_cast<float (*)[256]>(smem_raw + 4096 + g * 8192);   // [8][256]
    const int n0 = nb * 16 + g * 8;

    {
        float4* xs4 = reinterpret_cast<float4*>(&xs[0][0]);
        const float4* x4 = reinterpret_cast<const float4*>(x);
#pragma unroll
        for (int i = t64; i < 128; i += 64) {
            int node = n0 + (i >> 4);
            float4 v = make_float4(0.f, 0.f, 0.f, 0.f);
            if (node < N) v = x4[(size_t)node * 16 + (i & 15)];
            xs4[i] = v;
        }
    }
    __syncthreads();

    // GEMM1: 4 cols/thread (t64, +64, +128, +192) x 8 nodes
    {
        float a[4][8];
#pragma unroll
        for (int cc = 0; cc < 4; cc++)
#pragma unroll
            for (int m = 0; m < 8; m++) a[cc][m] = 0.f;

#pragma unroll 2
        for (int k4 = 0; k4 < 16; k4++) {
            float wr[4][4];
#pragma unroll
            for (int cc = 0; cc < 4; cc++)
#pragma unroll
                for (int j = 0; j < 4; j++)
                    wr[cc][j] = w1[(k4 * 4 + j) * 256 + t64 + 64 * cc];
#pragma unroll
            for (int m = 0; m < 8; m++) {
                float4 xv = *reinterpret_cast<const float4*>(&xs[m][k4 * 4]);
                float xa[4] = {xv.x, xv.y, xv.z, xv.w};
#pragma unroll
                for (int cc = 0; cc < 4; cc++)
#pragma unroll
                    for (int j = 0; j < 4; j++)
                        a[cc][m] = fmaf(xa[j], wr[cc][j], a[cc][m]);
            }
        }
#pragma unroll
        for (int cc = 0; cc < 4; cc++) {
            float bb = b1[t64 + 64 * cc];
#pragma unroll
            for (int m = 0; m < 8; m++) hs[m][t64 + 64 * cc] = a[cc][m] + bb;
        }
    }
    __syncthreads();

    // LN + GELU: 8 elems/lane, 2 warps per subgroup x 4 nodes
    {
        const int w2i = t64 >> 5, lane = t & 31;
        float rg[8], rb[8];
#pragma unroll
        for (int q = 0; q < 8; q++) { rg[q] = gm[lane + 32 * q]; rb[q] = bt[lane + 32 * q]; }
        for (int mm = 0; mm < 4; mm++) {
            int m = w2i * 4 + mm;
            float v[8];
            float sum = 0.f, sq = 0.f;
#pragma unroll
            for (int q = 0; q < 8; q++) {
                v[q] = hs[m][lane + 32 * q];
                sum += v[q];
                sq = fmaf(v[q], v[q], sq);
            }
            sum = wredsum(sum);
            sq = wredsum(sq);
            float mean = sum * (1.f / 256.f);
            float var = sq * (1.f / 256.f) - mean * mean;
            float rstd = rsqrtf(var + EPS_LN);
#pragma unroll
            for (int q = 0; q < 8; q++) {
                float u = fmaf((v[q] - mean) * rstd, rg[q], rb[q]);
                hs[m][lane + 32 * q] = gelu_fast(u);
            }
        }
    }
    __syncthreads();

    // GEMM2: OUT=128, thread = (mgroup of 4 nodes, 4 outputs)
    {
        const int mg = t64 >> 5;
        const int o0 = (t & 31) * 4;
        float acc[4][4];
#pragma unroll
        for (int mm = 0; mm < 4; mm++)
#pragma unroll
            for (int oo = 0; oo < 4; oo++) acc[mm][oo] = 0.f;

#pragma unroll 2
        for (int j4 = 0; j4 < 64; j4++) {
            float4 wv[4];
#pragma unroll
            for (int j = 0; j < 4; j++)
                wv[j] = *reinterpret_cast<const float4*>(&w2[(j4 * 4 + j) * 128 + o0]);
#pragma unroll
            for (int mm = 0; mm < 4; mm++) {
                int m = mg * 4 + mm;
                float4 gv = *reinterpret_cast<const float4*>(&hs[m][j4 * 4]);
                float gvals[4] = {gv.x, gv.y, gv.z, gv.w};
#pragma unroll
                for (int j = 0; j < 4; j++) {
                    acc[mm][0] = fmaf(gvals[j], wv[j].x, acc[mm][0]);
                    acc[mm][1] = fmaf(gvals[j], wv[j].y, acc[mm][1]);
                    acc[mm][2] = fmaf(gvals[j], wv[j].z, acc[mm][2]);
                    acc[mm][3] = fmaf(gvals[j], wv[j].w, acc[mm][3]);
                }
            }
        }
        float4 bo = *reinterpret_cast<const float4*>(&b2[o0]);
#pragma unroll
        for (int mm = 0; mm < 4; mm++) {
            int n = n0 + mg * 4 + mm;
            if (n < N) {
                float4 r;
                r.x = acc[mm][0] + bo.x;
                r.y = acc[mm][1] + bo.y;
                r.z = acc[mm][2] + bo.z;
                r.w = acc[mm][3] + bo.w;
                *reinterpret_cast<float4*>(&out[(size_t)n * 128 + o0]) = r;
            }
        }
    }
}

// ============================================================================
// Mega kernel: role-interleaved edge + fr + ph (8:3 block pattern)
// ============================================================================
__global__ __launch_bounds__(128, 8) void k_mega(
    const float* __restrict__ x, const int* __restrict__ ei, int N, int E,
    const float* __restrict__ fr_w1, const float* __restrict__ fr_b1,
    const float* __restrict__ fr_g, const float* __restrict__ fr_be,
    const float* __restrict__ fr_w2, const float* __restrict__ fr_b2,
    const float* __restrict__ ph_w1, const float* __restrict__ ph_b1,
    const float* __restrict__ ph_g, const float* __restrict__ ph_be,
    const float* __restrict__ ph_w2, const float* __restrict__ ph_b2,
    const float* __restrict__ sp_g, const float* __restrict__ sp_be,
    const float* __restrict__ sp_w2, const float* __restrict__ sp_b2,
    float* __restrict__ out_sp, float* __restrict__ out_fr, float* __restrict__ out_ph,
    int nfr, int nph) {
    __shared__ __align__(16) char smem_raw[24576];
    const int b = blockIdx.x;
    const int gid = b / 11;
    const int slot = b - gid * 11;

    if (slot < 8) {
        edge_role(gid * 8 + slot, ei, E, sp_g, sp_be, sp_w2, sp_b2, out_sp);
    } else {
        int nb = gid * 3 + (slot - 8);
        if (nb < nfr) {
            fr_role(nb, smem_raw, x, fr_w1, fr_b1, fr_g, fr_be, fr_w2, fr_b2, out_fr, N);
        } else if (nb < nfr + nph) {
            ph_role(nb - nfr, smem_raw, x, ph_w1, ph_b1, ph_g, ph_be, ph_w2, ph_b2, out_ph, N);
        }
    }
}

// ============================================================================
// launch
// ============================================================================
extern "C" void kernel_launch(void* const* d_in, const int* in_sizes, int n_in,
                              void* d_out, int out_size) {
    const float* x = (const float*)d_in[0];
    const int* ei = (const int*)d_in[1];
    const float* sp_w1 = (const float*)d_in[2];
    const float* sp_b1 = (const float*)d_in[3];
    const float* sp_g = (const float*)d_in[4];
    const float* sp_be = (const float*)d_in[5];
    const float* sp_w2 = (const float*)d_in[6];
    const float* sp_b2 = (const float*)d_in[7];
    const float* fr_w1 = (const float*)d_in[8];
    const float* fr_b1 = (const float*)d_in[9];
    const float* fr_g = (const float*)d_in[10];
    const float* fr_be = (const float*)d_in[11];
    const float* fr_w2 = (const float*)d_in[12];
    const float* fr_b2 = (const float*)d_in[13];
    const float* ph_w1 = (const float*)d_in[14];
    const float* ph_b1 = (const float*)d_in[15];
    const float* ph_g = (const float*)d_in[16];
    const float* ph_be = (const float*)d_in[17];
    const float* ph_w2 = (const float*)d_in[18];
    const float* ph_b2 = (const float*)d_in[19];

    const int N = in_sizes[0] / 64;
    const int E = in_sizes[1] / 2;

    float* out_sp = (float*)d_out;             // [E]
    float* out_fr = out_sp + (size_t)E;        // [N,64]
    float* out_ph = out_fr + (size_t)N * 64;   // [N,128]

    // Phase 1: P/Q precompute (edge branch depends on it)
    k_pq<<<(N + 15) / 16, 128>>>(x, sp_w1, sp_b1, N);

    // Phase 2: role-interleaved mega kernel
    const int nfr = (N + 31) / 32;
    const int nph = (N + 15) / 16;
    const int node_blocks = nfr + nph;
    const long ewarps = ((long)E + EPW - 1) / EPW;
    const int eblk = (int)((ewarps + 3) / 4);
    int Ga = (node_blocks + 2) / 3;
    int Gb = (eblk + 7) / 8;
    int G = Ga > Gb ? Ga : Gb;

    k_mega<<<G * 11, 128>>>(x, ei, N, E,
                            fr_w1, fr_b1, fr_g, fr_be, fr_w2, fr_b2,
                            ph_w1, ph_b1, ph_g, ph_be, ph_w2, ph_b2,
                            sp_g, sp_be, sp_w2, sp_b2,
                            out_sp, out_fr, out_ph, nfr, nph);
}

// round 6
// speedup vs baseline: 1.1433x; 1.0477x over previous
#include <cuda_runtime.h>
#include <math.h>

#define NMAX 50000
#define EPS_LN 1e-5f
#define EPW 16

typedef unsigned long long u64;

// Scratch: P = x @ sp_w1[0:64,:] + sp_b1, Q = x @ sp_w1[64:128,:]   (each [N,256])
__device__ float g_P[(size_t)NMAX * 256];
__device__ float g_Q[(size_t)NMAX * 256];

// ---------------- f32x2 packed helpers ----------------
__device__ __forceinline__ u64 f2pack(float lo, float hi) {
    u64 r; asm("mov.b64 %0, {%1, %2};" : "=l"(r) : "f"(lo), "f"(hi)); return r;
}
__device__ __forceinline__ void f2unpack(u64 v, float& lo, float& hi) {
    asm("mov.b64 {%0, %1}, %2;" : "=f"(lo), "=f"(hi) : "l"(v));
}
__device__ __forceinline__ u64 dup2(float v) { return f2pack(v, v); }
__device__ __forceinline__ u64 fma2(u64 a, u64 b, u64 c) {
    u64 d; asm("fma.rn.f32x2 %0, %1, %2, %3;" : "=l"(d) : "l"(a), "l"(b), "l"(c)); return d;
}
__device__ __forceinline__ u64 add2(u64 a, u64 b) {
    u64 d; asm("add.rn.f32x2 %0, %1, %2;" : "=l"(d) : "l"(a), "l"(b)); return d;
}
__device__ __forceinline__ u64 mul2(u64 a, u64 b) {
    u64 d; asm("mul.rn.f32x2 %0, %1, %2;" : "=l"(d) : "l"(a), "l"(b)); return d;
}
__device__ __forceinline__ float rcp_fast(float x) {
    float r; asm("rcp.approx.f32 %0, %1;" : "=f"(r) : "f"(x)); return r;
}
__device__ __forceinline__ float ex2_fast(float x) {
    float r; asm("ex2.approx.f32 %0, %1;" : "=f"(r) : "f"(x)); return r;
}

__device__ __forceinline__ float wredsum(float v) {
#pragma unroll
    for (int o = 16; o > 0; o >>= 1) v += __shfl_xor_sync(0xffffffffu, v, o);
    return v;
}

// interleaved dual butterfly reduction: two independent chains overlap SHFL latency
__device__ __forceinline__ void wredsum2(float& a, float& b) {
#pragma unroll
    for (int o = 16; o > 0; o >>= 1) {
        float ta = __shfl_xor_sync(0xffffffffu, a, o);
        float tb = __shfl_xor_sync(0xffffffffu, b, o);
        a += ta;
        b += tb;
    }
}

// fast GELU via Hastings 3-term erf (A&S 7.1.25, |err| <= 2.5e-5)
__device__ __forceinline__ float gelu_fast(float u) {
    float z = 0.70710678118654752f * u;
    float az = fabsf(z);
    float t = rcp_fast(fmaf(0.47047f, az, 1.0f));
    float poly = t * fmaf(t, fmaf(t, 0.7478556f, -0.0958798f), 0.3480242f);
    float e = ex2_fast(-az * az * 1.4426950408889634f);
    float erf_z = copysignf(fmaf(-poly, e, 1.0f), z);
    return 0.5f * u * (1.0f + erf_z);
}

// ============================================================================
// K1: P,Q = x @ W_top (+b1), x @ W_bot.  (scalar FMA roofline version)
// ============================================================================
__global__ __launch_bounds__(128) void k_pq(const float* __restrict__ x,
                                            const float* __restrict__ w,   // [128,256]
                                            const float* __restrict__ b1,  // [256]
                                            int N) {
    __shared__ float xs[16][64];
    const int t = threadIdx.x;
    const int n0 = blockIdx.x * 16;

    {
        float4* xs4 = reinterpret_cast<float4*>(&xs[0][0]);
        const float4* x4 = reinterpret_cast<const float4*>(x);
#pragma unroll
        for (int i = t; i < 256; i += 128) {
            int node = n0 + (i >> 4);
            float4 v = make_float4(0.f, 0.f, 0.f, 0.f);
            if (node < N) v = x4[(size_t)node * 16 + (i & 15)];
            xs4[i] = v;
        }
    }
    __syncthreads();

    float aP0[16], aP1[16], aQ0[16], aQ1[16];
#pragma unroll
    for (int m = 0; m < 16; m++) { aP0[m] = 0.f; aP1[m] = 0.f; aQ0[m] = 0.f; aQ1[m] = 0.f; }

    const int c0 = t, c1 = t + 128;
#pragma unroll 2
    for (int k4 = 0; k4 < 16; k4++) {
        float wp0[4], wp1[4], wq0[4], wq1[4];
#pragma unroll
        for (int j = 0; j < 4; j++) {
            int k = k4 * 4 + j;
            wp0[j] = w[k * 256 + c0];
            wp1[j] = w[k * 256 + c1];
            wq0[j] = w[(64 + k) * 256 + c0];
            wq1[j] = w[(64 + k) * 256 + c1];
        }
#pragma unroll
        for (int m = 0; m < 16; m++) {
            float4 xv = *reinterpret_cast<const float4*>(&xs[m][k4 * 4]);
            float xa[4] = {xv.x, xv.y, xv.z, xv.w};
#pragma unroll
            for (int j = 0; j < 4; j++) {
                aP0[m] = fmaf(xa[j], wp0[j], aP0[m]);
                aP1[m] = fmaf(xa[j], wp1[j], aP1[m]);
                aQ0[m] = fmaf(xa[j], wq0[j], aQ0[m]);
                aQ1[m] = fmaf(xa[j], wq1[j], aQ1[m]);
            }
        }
    }

    const float bb0 = b1[c0], bb1 = b1[c1];
#pragma unroll
    for (int m = 0; m < 16; m++) {
        int n = n0 + m;
        if (n >= N) break;
        g_P[(size_t)n * 256 + c0] = aP0[m] + bb0;
        g_P[(size_t)n * 256 + c1] = aP1[m] + bb1;
        g_Q[(size_t)n * 256 + c0] = aQ0[m];
        g_Q[(size_t)n * 256 + c1] = aQ1[m];
    }
}

// ============================================================================
// Edge role: out = GELU(LN(P[row]+Q[col])) . w2 + b2
// f32x2 math, interleaved reductions, vectorized index load, 1-ahead prefetch.
// ============================================================================
__device__ __forceinline__ void edge_role(int eb, const int* __restrict__ ei, int E,
                                          const float* __restrict__ gm,
                                          const float* __restrict__ bt,
                                          const float* __restrict__ w2,
                                          const float* __restrict__ b2p,
                                          float* __restrict__ out) {
    const int t = threadIdx.x;
    const int lane = t & 31;
    const int wid = t >> 5;

    long e0 = ((long)eb * 4 + wid) * EPW;
    if (e0 >= E) return;
    const int nE = (int)(E - e0 < EPW ? E - e0 : EPW);

    const float4* gmv = reinterpret_cast<const float4*>(gm);
    const float4* btv = reinterpret_cast<const float4*>(bt);
    const float4* w2v = reinterpret_cast<const float4*>(w2);
    float4 rga = gmv[lane], rgb = gmv[32 + lane];
    float4 rba = btv[lane], rbb = btv[32 + lane];
    float4 rwa = w2v[lane], rwb = w2v[32 + lane];

    const float RS2 = 0.70710678118654752f;  // 1/sqrt2 (also = 0.5*sqrt2)
    u64 g2[4] = {f2pack(rga.x * RS2, rga.y * RS2), f2pack(rga.z * RS2, rga.w * RS2),
                 f2pack(rgb.x * RS2, rgb.y * RS2), f2pack(rgb.z * RS2, rgb.w * RS2)};
    u64 be2[4] = {f2pack(rba.x * RS2, rba.y * RS2), f2pack(rba.z * RS2, rba.w * RS2),
                  f2pack(rbb.x * RS2, rbb.y * RS2), f2pack(rbb.z * RS2, rbb.w * RS2)};
    u64 hw2[4] = {f2pack(rwa.x * RS2, rwa.y * RS2), f2pack(rwa.z * RS2, rwa.w * RS2),
                  f2pack(rwb.x * RS2, rwb.y * RS2), f2pack(rwb.z * RS2, rwb.w * RS2)};

    const u64 ONE2 = dup2(1.0f);
    const u64 PC = dup2(0.47047f);
    const u64 C3 = dup2(-0.7478556f);
    const u64 C2C = dup2(0.0958798f);
    const u64 C1 = dup2(-0.3480242f);
    const u64 NL2E = dup2(-1.4426950408889634f);
    const u64 AMASK = 0x7FFFFFFF7FFFFFFFull;
    const u64 SMASK = 0x8000000080000000ull;

    const float b2 = __ldg(b2p);

    const ulonglong2* P2v = reinterpret_cast<const ulonglong2*>(g_P);
    const ulonglong2* Q2v = reinterpret_cast<const ulonglong2*>(g_Q);

    // vectorized index load: lanes 0-15 row idx, lanes 16-31 col idx
    const int li = lane & 15;
    int idx = 0;
    if (li < nE) idx = ei[(lane < 16 ? e0 + li : (long)E + e0 + li)];

    // prefetch edge 0
    int r = __shfl_sync(0xffffffffu, idx, 0);
    int c = __shfl_sync(0xffffffffu, idx, 16);
    ulonglong2 pa = P2v[(size_t)r * 64 + lane];
    ulonglong2 pb = P2v[(size_t)r * 64 + 32 + lane];
    ulonglong2 qa = Q2v[(size_t)c * 64 + lane];
    ulonglong2 qb = Q2v[(size_t)c * 64 + 32 + lane];

    for (int i = 0; i < nE; i++) {
        // prefetch edge i+1 (uniform branch)
        ulonglong2 pan = pa, pbn = pb, qan = qa, qbn = qb;
        if (i + 1 < nE) {
            int rn = __shfl_sync(0xffffffffu, idx, i + 1);
            int cn = __shfl_sync(0xffffffffu, idx, 17 + i);
            pan = P2v[(size_t)rn * 64 + lane];
            pbn = P2v[(size_t)rn * 64 + 32 + lane];
            qan = Q2v[(size_t)cn * 64 + lane];
            qbn = Q2v[(size_t)cn * 64 + 32 + lane];
        }

        u64 s0 = add2(pa.x, qa.x), s1 = add2(pa.y, qa.y);
        u64 s2 = add2(pb.x, qb.x), s3 = add2(pb.y, qb.y);

        u64 sum2 = add2(add2(s0, s1), add2(s2, s3));
        u64 sq2 = fma2(s0, s0, fma2(s1, s1, fma2(s2, s2, mul2(s3, s3))));
        float slo, shi, sqlo, sqhi;
        f2unpack(sum2, slo, shi);
        f2unpack(sq2, sqlo, sqhi);
        float sum = slo + shi;
        float sq = sqlo + sqhi;
        wredsum2(sum, sq);
        float mean = sum * (1.f / 256.f);
        float var = sq * (1.f / 256.f) - mean * mean;
        float rstd = rsqrtf(var + EPS_LN);
        u64 A2 = dup2(rstd);
        u64 Cc = dup2(-mean * rstd);

        u64 sarr[4] = {s0, s1, s2, s3};
        u64 acc2 = 0;
#pragma unroll
        for (int p = 0; p < 4; p++) {
            u64 un2 = fma2(sarr[p], A2, Cc);    // normalized
            u64 z2 = fma2(un2, g2[p], be2[p]);  // z = (norm*g + be)/sqrt2 (folded)
            u64 az2 = z2 & AMASK;
            u64 d2 = fma2(az2, PC, ONE2);
            float dl, dh;
            f2unpack(d2, dl, dh);
            u64 t2 = f2pack(rcp_fast(dl), rcp_fast(dh));
            u64 p2 = fma2(t2, C3, C2C);
            p2 = fma2(t2, p2, C1);
            p2 = mul2(p2, t2);                  // n(t): erf = 1 + n*e
            u64 zz2 = mul2(az2, az2);
            u64 m2 = mul2(zz2, NL2E);
            float ml, mh;
            f2unpack(m2, ml, mh);
            u64 e2 = f2pack(ex2_fast(ml), ex2_fast(mh));
            u64 erf2 = fma2(p2, e2, ONE2);      // |erf(z)|
            erf2 = erf2 | (z2 & SMASK);         // sign of z
            u64 op2 = add2(erf2, ONE2);         // 1 + erf
            u64 term2 = mul2(z2, op2);          // z*(1+erf)
            acc2 = fma2(term2, hw2[p], acc2);   // * (w2*sqrt2/2)
        }
        float al, ah;
        f2unpack(acc2, al, ah);
        float acc = wredsum(al + ah);
        if (lane == 0) out[e0 + i] = acc + b2;

        pa = pan; pb = pbn; qa = qan; qb = qbn;
    }
}

// ============================================================================
// fr role: x[64] -> Linear(128) -> LN -> GELU -> Linear(64)
// Two 64-thread subgroups, 16 nodes each (32 nodes/block). Scalar FMA.
// ============================================================================
__device__ __forceinline__ void fr_role(int nb, char* smem_raw,
                                        const float* __restrict__ x,
                                        const float* __restrict__ w1,
                                        const float* __restrict__ b1,
                                        const float* __restrict__ gm,
                                        const float* __restrict__ bt,
                                        const float* __restrict__ w2,
                                        const float* __restrict__ b2,
                                        float* __restrict__ out, int N) {
    const int t = threadIdx.x;
    const int g = t >> 6;
    const int t64 = t & 63;
    float (*xs)[64] = reinterpret_cast<float (*)[64]>(smem_raw + g * 4096);
    float (*hs)[128] = reinterpret_cast<float (*)[128]>(smem_raw + 8192 + g * 8192);
    const int n0 = nb * 32 + g * 16;

    {
        float4* xs4 = reinterpret_cast<float4*>(&xs[0][0]);
        const float4* x4 = reinterpret_cast<const float4*>(x);
#pragma unroll
        for (int i = t64; i < 256; i += 64) {
            int node = n0 + (i >> 4);
            float4 v = make_float4(0.f, 0.f, 0.f, 0.f);
            if (node < N) v = x4[(size_t)node * 16 + (i & 15)];
            xs4[i] = v;
        }
    }
    __syncthreads();

    {
        float a0[16], a1[16];
#pragma unroll
        for (int m = 0; m < 16; m++) { a0[m] = 0.f; a1[m] = 0.f; }
        const int c0 = t64, c1 = t64 + 64;
#pragma unroll 2
        for (int k4 = 0; k4 < 16; k4++) {
            float wr0[4], wr1[4];
#pragma unroll
            for (int j = 0; j < 4; j++) {
                int k = k4 * 4 + j;
                wr0[j] = w1[k * 128 + c0];
                wr1[j] = w1[k * 128 + c1];
            }
#pragma unroll
            for (int m = 0; m < 16; m++) {
                float4 xv = *reinterpret_cast<const float4*>(&xs[m][k4 * 4]);
                float xa[4] = {xv.x, xv.y, xv.z, xv.w};
#pragma unroll
                for (int j = 0; j < 4; j++) {
                    a0[m] = fmaf(xa[j], wr0[j], a0[m]);
                    a1[m] = fmaf(xa[j], wr1[j], a1[m]);
                }
            }
        }
        float bb0 = b1[c0], bb1 = b1[c1];
#pragma unroll
        for (int m = 0; m < 16; m++) { hs[m][c0] = a0[m] + bb0; hs[m][c1] = a1[m] + bb1; }
    }
    __syncthreads();

    {
        const int w2i = t64 >> 5, lane = t & 31;
        float rg[4], rb[4];
#pragma unroll
        for (int q = 0; q < 4; q++) { rg[q] = gm[lane + 32 * q]; rb[q] = bt[lane + 32 * q]; }
        for (int mm = 0; mm < 8; mm++) {
            int m = w2i * 8 + mm;
            float v[4];
            float sum = 0.f, sq = 0.f;
#pragma unroll
            for (int q = 0; q < 4; q++) {
                v[q] = hs[m][lane + 32 * q];
                sum += v[q];
                sq = fmaf(v[q], v[q], sq);
            }
            wredsum2(sum, sq);
            float mean = sum * (1.f / 128.f);
            float var = sq * (1.f / 128.f) - mean * mean;
            float rstd = rsqrtf(var + EPS_LN);
#pragma unroll
            for (int q = 0; q < 4; q++) {
                float u = fmaf((v[q] - mean) * rstd, rg[q], rb[q]);
                hs[m][lane + 32 * q] = gelu_fast(u);
            }
        }
    }
    __syncthreads();

    {
        const int mg = t64 >> 5;
        const int o0 = (t & 31) * 2;
        float acc[8][2];
#pragma unroll
        for (int mm = 0; mm < 8; mm++) { acc[mm][0] = 0.f; acc[mm][1] = 0.f; }
#pragma unroll 2
        for (int j4 = 0; j4 < 32; j4++) {
            float2 wv[4];
#pragma unroll
            for (int j = 0; j < 4; j++)
                wv[j] = *reinterpret_cast<const float2*>(&w2[(j4 * 4 + j) * 64 + o0]);
#pragma unroll
            for (int mm = 0; mm < 8; mm++) {
                int m = mg * 8 + mm;
                float4 gv = *reinterpret_cast<const float4*>(&hs[m][j4 * 4]);
                acc[mm][0] = fmaf(gv.x, wv[0].x, acc[mm][0]);
                acc[mm][0] = fmaf(gv.y, wv[1].x, acc[mm][0]);
                acc[mm][0] = fmaf(gv.z, wv[2].x, acc[mm][0]);
                acc[mm][0] = fmaf(gv.w, wv[3].x, acc[mm][0]);
                acc[mm][1] = fmaf(gv.x, wv[0].y, acc[mm][1]);
                acc[mm][1] = fmaf(gv.y, wv[1].y, acc[mm][1]);
                acc[mm][1] = fmaf(gv.z, wv[2].y, acc[mm][1]);
                acc[mm][1] = fmaf(gv.w, wv[3].y, acc[mm][1]);
            }
        }
        float bo0 = b2[o0], bo1 = b2[o0 + 1];
#pragma unroll
        for (int mm = 0; mm < 8; mm++) {
            int n = n0 + mg * 8 + mm;
            if (n < N) {
                out[(size_t)n * 64 + o0] = acc[mm][0] + bo0;
                out[(size_t)n * 64 + o0 + 1] = acc[mm][1] + bo1;
            }
        }
    }
}

// ============================================================================
// ph role: x[64] -> Linear(256) -> LN -> GELU -> Linear(128)
// Two 64-thread subgroups, 8 nodes each (16 nodes/block). Scalar FMA.
// ============================================================================
__device__ __forceinline__ void ph_role(int nb, char* smem_raw,
                                        const float* __restrict__ x,
                                        const float* __restrict__ w1,
                                        const float* __restrict__ b1,
                                        const float* __restrict__ gm,
                                        const float* __restrict__ bt,
                                        const float* __restrict__ w2,
                                        const float* __restrict__ b2,
                                        float* __restrict__ out, int N) {
    const int t = threadIdx.x;
    const int g = t >> 6;
    const int t64 = t & 63;
    float (*xs)[64] = reinterpret_cast<float (*)[64]>(smem_raw + g * 2048);
    float (*hs)[256] = reinterpret_cast<float (*)[256]>(smem_raw + 4096 + g * 8192);
    const int n0 = nb * 16 + g * 8;

    {
        float4* xs4 = reinterpret_cast<float4*>(&xs[0][0]);
        const float4* x4 = reinterpret_cast<const float4*>(x);
#pragma unroll
        for (int i = t64; i < 128; i += 64) {
            int node = n0 + (i >> 4);
            float4 v = make_float4(0.f, 0.f, 0.f, 0.f);
            if (node < N) v = x4[(size_t)node * 16 + (i & 15)];
            xs4[i] = v;
        }
    }
    __syncthreads();

    {
        float a[4][8];
#pragma unroll
        for (int cc = 0; cc < 4; cc++)
#pragma unroll
            for (int m = 0; m < 8; m++) a[cc][m] = 0.f;

#pragma unroll 2
        for (int k4 = 0; k4 < 16; k4++) {
            float wr[4][4];
#pragma unroll
            for (int cc = 0; cc < 4; cc++)
#pragma unroll
                for (int j = 0; j < 4; j++)
                    wr[cc][j] = w1[(k4 * 4 + j) * 256 + t64 + 64 * cc];
#pragma unroll
            for (int m = 0; m < 8; m++) {
                float4 xv = *reinterpret_cast<const float4*>(&xs[m][k4 * 4]);
                float xa[4] = {xv.x, xv.y, xv.z, xv.w};
#pragma unroll
                for (int cc = 0; cc < 4; cc++)
#pragma unroll
                    for (int j = 0; j < 4; j++)
                        a[cc][m] = fmaf(xa[j], wr[cc][j], a[cc][m]);
            }
        }
#pragma unroll
        for (int cc = 0; cc < 4; cc++) {
            float bb = b1[t64 + 64 * cc];
#pragma unroll
            for (int m = 0; m < 8; m++) hs[m][t64 + 64 * cc] = a[cc][m] + bb;
        }
    }
    __syncthreads();

    {
        const int w2i = t64 >> 5, lane = t & 31;
        float rg[8], rb[8];
#pragma unroll
        for (int q = 0; q < 8; q++) { rg[q] = gm[lane + 32 * q]; rb[q] = bt[lane + 32 * q]; }
        for (int mm = 0; mm < 4; mm++) {
            int m = w2i * 4 + mm;
            float v[8];
            float sum = 0.f, sq = 0.f;
#pragma unroll
            for (int q = 0; q < 8; q++) {
                v[q] = hs[m][lane + 32 * q];
                sum += v[q];
                sq = fmaf(v[q], v[q], sq);
            }
            wredsum2(sum, sq);
            float mean = sum * (1.f / 256.f);
            float var = sq * (1.f / 256.f) - mean * mean;
            float rstd = rsqrtf(var + EPS_LN);
#pragma unroll
            for (int q = 0; q < 8; q++) {
                float u = fmaf((v[q] - mean) * rstd, rg[q], rb[q]);
                hs[m][lane + 32 * q] = gelu_fast(u);
            }
        }
    }
    __syncthreads();

    {
        const int mg = t64 >> 5;
        const int o0 = (t & 31) * 4;
        float acc[4][4];
#pragma unroll
        for (int mm = 0; mm < 4; mm++)
#pragma unroll
            for (int oo = 0; oo < 4; oo++) acc[mm][oo] = 0.f;

#pragma unroll 2
        for (int j4 = 0; j4 < 64; j4++) {
            float4 wv[4];
#pragma unroll
            for (int j = 0; j < 4; j++)
                wv[j] = *reinterpret_cast<const float4*>(&w2[(j4 * 4 + j) * 128 + o0]);
#pragma unroll
            for (int mm = 0; mm < 4; mm++) {
                int m = mg * 4 + mm;
                float4 gv = *reinterpret_cast<const float4*>(&hs[m][j4 * 4]);
                float gvals[4] = {gv.x, gv.y, gv.z, gv.w};
#pragma unroll
                for (int j = 0; j < 4; j++) {
                    acc[mm][0] = fmaf(gvals[j], wv[j].x, acc[mm][0]);
                    acc[mm][1] = fmaf(gvals[j], wv[j].y, acc[mm][1]);
                    acc[mm][2] = fmaf(gvals[j], wv[j].z, acc[mm][2]);
                    acc[mm][3] = fmaf(gvals[j], wv[j].w, acc[mm][3]);
                }
            }
        }
        float4 bo = *reinterpret_cast<const float4*>(&b2[o0]);
#pragma unroll
        for (int mm = 0; mm < 4; mm++) {
            int n = n0 + mg * 4 + mm;
            if (n < N) {
                float4 rr;
                rr.x = acc[mm][0] + bo.x;
                rr.y = acc[mm][1] + bo.y;
                rr.z = acc[mm][2] + bo.z;
                rr.w = acc[mm][3] + bo.w;
                *reinterpret_cast<float4*>(&out[(size_t)n * 128 + o0]) = rr;
            }
        }
    }
}

// ============================================================================
// Mega kernel: role-interleaved edge + fr + ph (8:3 block pattern)
// ============================================================================
__global__ __launch_bounds__(128, 6) void k_mega(
    const float* __restrict__ x, const int* __restrict__ ei, int N, int E,
    const float* __restrict__ fr_w1, const float* __restrict__ fr_b1,
    const float* __restrict__ fr_g, const float* __restrict__ fr_be,
    const float* __restrict__ fr_w2, const float* __restrict__ fr_b2,
    const float* __restrict__ ph_w1, const float* __restrict__ ph_b1,
    const float* __restrict__ ph_g, const float* __restrict__ ph_be,
    const float* __restrict__ ph_w2, const float* __restrict__ ph_b2,
    const float* __restrict__ sp_g, const float* __restrict__ sp_be,
    const float* __restrict__ sp_w2, const float* __restrict__ sp_b2,
    float* __restrict__ out_sp, float* __restrict__ out_fr, float* __restrict__ out_ph,
    int nfr, int nph) {
    __shared__ __align__(16) char smem_raw[24576];
    const int b = blockIdx.x;
    const int gid = b / 11;
    const int slot = b - gid * 11;

    if (slot < 8) {
        edge_role(gid * 8 + slot, ei, E, sp_g, sp_be, sp_w2, sp_b2, out_sp);
    } else {
        int nb = gid * 3 + (slot - 8);
        if (nb < nfr) {
            fr_role(nb, smem_raw, x, fr_w1, fr_b1, fr_g, fr_be, fr_w2, fr_b2, out_fr, N);
        } else if (nb < nfr + nph) {
            ph_role(nb - nfr, smem_raw, x, ph_w1, ph_b1, ph_g, ph_be, ph_w2, ph_b2, out_ph, N);
        }
    }
}

// ============================================================================
// launch
// ============================================================================
extern "C" void kernel_launch(void* const* d_in, const int* in_sizes, int n_in,
                              void* d_out, int out_size) {
    const float* x = (const float*)d_in[0];
    const int* ei = (const int*)d_in[1];
    const float* sp_w1 = (const float*)d_in[2];
    const float* sp_b1 = (const float*)d_in[3];
    const float* sp_g = (const float*)d_in[4];
    const float* sp_be = (const float*)d_in[5];
    const float* sp_w2 = (const float*)d_in[6];
    const float* sp_b2 = (const float*)d_in[7];
    const float* fr_w1 = (const float*)d_in[8];
    const float* fr_b1 = (const float*)d_in[9];
    const float* fr_g = (const float*)d_in[10];
    const float* fr_be = (const float*)d_in[11];
    const float* fr_w2 = (const float*)d_in[12];
    const float* fr_b2 = (const float*)d_in[13];
    const float* ph_w1 = (const float*)d_in[14];
    const float* ph_b1 = (const float*)d_in[15];
    const float* ph_g = (const float*)d_in[16];
    const float* ph_be = (const float*)d_in[17];
    const float* ph_w2 = (const float*)d_in[18];
    const float* ph_b2 = (const float*)d_in[19];

    const int N = in_sizes[0] / 64;
    const int E = in_sizes[1] / 2;

    float* out_sp = (float*)d_out;             // [E]
    float* out_fr = out_sp + (size_t)E;        // [N,64]
    float* out_ph = out_fr + (size_t)N * 64;   // [N,128]

    // Phase 1: P/Q precompute (edge branch depends on it)
    k_pq<<<(N + 15) / 16, 128>>>(x, sp_w1, sp_b1, N);

    // Phase 2: role-interleaved mega kernel
    const int nfr = (N + 31) / 32;
    const int nph = (N + 15) / 16;
    const int node_blocks = nfr + nph;
    const long ewarps = ((long)E + EPW - 1) / EPW;
    const int eblk = (int)((ewarps + 3) / 4);
    int Ga = (node_blocks + 2) / 3;
    int Gb = (eblk + 7) / 8;
    int G = Ga > Gb ? Ga : Gb;

    k_mega<<<G * 11, 128>>>(x, ei, N, E,
                            fr_w1, fr_b1, fr_g, fr_be, fr_w2, fr_b2,
                            ph_w1, ph_b1, ph_g, ph_be, ph_w2, ph_b2,
                            sp_g, sp_be, sp_w2, sp_b2,
                            out_sp, out_fr, out_ph, nfr, nph);
}